// round 6
// baseline (speedup 1.0000x reference)
#include <cuda_runtime.h>

#define H   64
#define NH  4
#define MA  64
#define BS  64
#define E   256    // H*NH
#define MAXROWS 4096

// scratch (device globals: no allocation allowed)
// P layout for u rows: element e (l=e&31, k=e>>5) stored at
//   p = (k>>2)*128 + 4*l + (k&3)
// so lane l's 8 elements are two float4s at quads l and 32+l (conflict-free LDS).
__device__ float g_u[MAXROWS * E];
__device__ float g_molpart[BS * 4 * H];  // per-(b,quarter) molecule partials
__device__ int   g_count[BS];            // arrival counters (reset by kA each call)

__device__ __forceinline__ long long scope_at(const void* sp, int i, bool is64) {
    return is64 ? ((const long long*)sp)[i] : (long long)((const int*)sp)[i];
}
__device__ __forceinline__ bool scope_is64(const void* sp) {
    // scope flat: [1, 2, ...]; int32 -> word1 == 2 ; int64 -> word1 == 0
    return ((const int*)sp)[1] == 0;
}
__device__ __forceinline__ float sigmoid_fast(float s) {
    float t;
    asm("tanh.approx.f32 %0, %1;" : "=f"(t) : "f"(0.5f * s));
    return fmaf(0.5f, t, 0.5f);   // 0.5*(1+tanh(s/2)) == sigmoid(s)
}
__device__ __forceinline__ unsigned long long pack2(float x) {
    unsigned r = __float_as_uint(x);
    unsigned long long o;
    asm("mov.b64 %0, {%1, %1};" : "=l"(o) : "r"(r));
    return o;
}
#define FMA2(acc, a, b) asm("fma.rn.f32x2 %0, %1, %2, %0;" : "+l"(acc) : "l"(a), "l"(b))

// ---------------------------------------------------------------------------
// Kernel A: u_flat = inputs @ Wa_pair over N+1 flat rows, P-layout store.
// Wa_pair staged in smem (kills the 45MB L2 weight re-read).
// 8 rows/block -> 347 blocks. Also zeroes flat row 0 and the arrival counters.
// dyn smem: wa_s[64*256] + cs[8*64] = 67.5 KB
// ---------------------------------------------------------------------------
__global__ void __launch_bounds__(256) kA(const float* __restrict__ inputs,
                                          const float* __restrict__ Wa_pair,
                                          int n1, float* __restrict__ d_out) {
    extern __shared__ float sm[];
    float* wa_s = sm;            // 64 x 256 (row-major, logical)
    float* cs   = sm + H * E;    // 8 x 64
    const int t = threadIdx.x, blk = blockIdx.x;

    if (blk == 0) {
        if (t < 16)   // flat row 0 = pad row -> zeros
            ((float4*)(d_out + BS * H))[t] = make_float4(0.f, 0.f, 0.f, 0.f);
        if (t < BS) g_count[t] = 0;
    }

    // stage Wa_pair: 4096 float4, straight copy
#pragma unroll
    for (int it = 0; it < 16; it++)
        ((float4*)wa_s)[t + 256 * it] = __ldg(((const float4*)Wa_pair) + t + 256 * it);

    // stage 8 input rows (128 float4)
    if (t < 128) {
        int r = blk * 8 + (t >> 4), q = t & 15;
        float4 z = make_float4(0.f, 0.f, 0.f, 0.f);
        ((float4*)cs)[t] = (r < n1) ? ((const float4*)(inputs + (size_t)r * H))[q] : z;
    }
    __syncthreads();

    const int eg = t & 63, rg = t >> 6;   // 4 e-cols, 2 rows per thread
    const int e0 = eg * 4;
    float4 acc0 = make_float4(0.f, 0.f, 0.f, 0.f);
    float4 acc1 = make_float4(0.f, 0.f, 0.f, 0.f);

#pragma unroll 8
    for (int h = 0; h < H; h++) {
        float4 w = *(const float4*)(wa_s + h * E + e0);
        float c0 = cs[(rg * 2 + 0) * H + h];
        float c1 = cs[(rg * 2 + 1) * H + h];
        acc0.x = fmaf(c0, w.x, acc0.x);  acc0.y = fmaf(c0, w.y, acc0.y);
        acc0.z = fmaf(c0, w.z, acc0.z);  acc0.w = fmaf(c0, w.w, acc0.w);
        acc1.x = fmaf(c1, w.x, acc1.x);  acc1.y = fmaf(c1, w.y, acc1.y);
        acc1.z = fmaf(c1, w.z, acc1.z);  acc1.w = fmaf(c1, w.w, acc1.w);
    }

    float4 av[2] = {acc0, acc1};
#pragma unroll
    for (int m = 0; m < 2; m++) {
        int rr = blk * 8 + rg * 2 + m;
        if (rr < n1) {
            float* dst = g_u + (size_t)rr * E;
            float a4[4] = {av[m].x, av[m].y, av[m].z, av[m].w};
#pragma unroll
            for (int c = 0; c < 4; c++) {
                int e = e0 + c;
                int l = e & 31, k = e >> 5;
                dst[(k >> 2) * 128 + 4 * l + (k & 3)] = a4[c];
            }
        }
    }
}

// ---------------------------------------------------------------------------
// Kernel B (fused): pairwise attention + c_sum + projection + scatter + c_mol.
// grid (64, 4): (b, quarter of 16 i). 256 threads = 8 warps, 2 i per warp.
// dyn smem: region0[64*256] (u tile, then Wp) + region1[64*64] (c tile, then
//           csum 16x256, then reduction 16x64) = 80 KB -> 2 blocks/SM.
// ---------------------------------------------------------------------------
__global__ void __launch_bounds__(256) kB(const float* __restrict__ inputs,
                                          const void* __restrict__ scope,
                                          const float* __restrict__ Wa_score,
                                          const float* __restrict__ Wp,
                                          float* __restrict__ d_out) {
    extern __shared__ float sm[];
    float* up_s  = sm;              // phase 1: u tile (P layout); phase 2: Wp
    float* cbp_s = sm + MA * E;     // phase 1: c tile (quad-swizzled); phase 2: csum
    __shared__ int flag;

    const bool is64 = scope_is64(scope);
    const int b = blockIdx.x, qq = blockIdx.y;
    const int t = threadIdx.x, l = t & 31, wid = t >> 5;

    // lane l owns e = l + 32k  (head n = l&3 lane-constant -> 3-shuffle reduce)
    float ws[8];
#pragma unroll
    for (int k = 0; k < 8; k++) ws[k] = __ldg(Wa_score + l + 32 * k);

    // stage u rows (P layout in gmem) via scope: float4 both sides
#pragma unroll
    for (int it = 0; it < 16; it++) {
        int Q = t + 256 * it;            // 64 rows * 64 quads
        int j = Q >> 6, qd = Q & 63;
        long long s = scope_at(scope, b * MA + j, is64);
        ((float4*)up_s)[Q] = ((const float4*)(g_u + (size_t)s * E))[qd];
    }
    // stage c: h-group h quad qA=2h+(h>=4) holds m=0..3, qB=2h+1-(h>=4) m=4..7
#pragma unroll
    for (int it = 0; it < 4; it++) {
        int Q = t + 256 * it;            // 64 rows * 16 quads
        int j = Q >> 4, qd = Q & 15;
        long long s = scope_at(scope, b * MA + j, is64);
        const float* src = inputs + (size_t)s * H;
        int h = qd >> 1;
        int mb = ((qd & 1) == (qd >> 3)) ? 0 : 4;
        float4 v;
        v.x = src[h + 8 * (mb + 0)];
        v.y = src[h + 8 * (mb + 1)];
        v.z = src[h + 8 * (mb + 2)];
        v.w = src[h + 8 * (mb + 3)];
        ((float4*)cbp_s)[Q] = v;
    }
    __syncthreads();

    const int hq = l >> 2;
    const int qA = 2 * hq + (hq >> 2);       // h>=4 -> +1
    const int qB = 2 * hq + 1 - (hq >> 2);
    const int i0 = qq * 16 + wid, i1 = i0 + 8;

    const float4* uiA = (const float4*)(up_s + i0 * E);
    float4 A0 = uiA[l], A1 = uiA[32 + l];
    const float4* uiB = (const float4*)(up_s + i1 * E);
    float4 B0 = uiB[l], B1 = uiB[32 + l];

    unsigned long long csA[4] = {0, 0, 0, 0}, csB[4] = {0, 0, 0, 0};

#pragma unroll 4
    for (int j = 0; j < MA; j++) {
        const float4* ur = (const float4*)(up_s + j * E);
        float4 a0 = ur[l], a1 = ur[32 + l];
        float v, sA0, sA1, sB0, sB1;
        v = fmaxf(A0.x + a0.x, 0.f); sA0 = v * ws[0];
        v = fmaxf(A0.y + a0.y, 0.f); sA1 = v * ws[1];
        v = fmaxf(A0.z + a0.z, 0.f); sA0 = fmaf(v, ws[2], sA0);
        v = fmaxf(A0.w + a0.w, 0.f); sA1 = fmaf(v, ws[3], sA1);
        v = fmaxf(A1.x + a1.x, 0.f); sA0 = fmaf(v, ws[4], sA0);
        v = fmaxf(A1.y + a1.y, 0.f); sA1 = fmaf(v, ws[5], sA1);
        v = fmaxf(A1.z + a1.z, 0.f); sA0 = fmaf(v, ws[6], sA0);
        v = fmaxf(A1.w + a1.w, 0.f); sA1 = fmaf(v, ws[7], sA1);

        v = fmaxf(B0.x + a0.x, 0.f); sB0 = v * ws[0];
        v = fmaxf(B0.y + a0.y, 0.f); sB1 = v * ws[1];
        v = fmaxf(B0.z + a0.z, 0.f); sB0 = fmaf(v, ws[2], sB0);
        v = fmaxf(B0.w + a0.w, 0.f); sB1 = fmaf(v, ws[3], sB1);
        v = fmaxf(B1.x + a1.x, 0.f); sB0 = fmaf(v, ws[4], sB0);
        v = fmaxf(B1.y + a1.y, 0.f); sB1 = fmaf(v, ws[5], sB1);
        v = fmaxf(B1.z + a1.z, 0.f); sB0 = fmaf(v, ws[6], sB0);
        v = fmaxf(B1.w + a1.w, 0.f); sB1 = fmaf(v, ws[7], sB1);

        float sA = sA0 + sA1, sB = sB0 + sB1;
        sA += __shfl_xor_sync(0xffffffffu, sA, 4);
        sB += __shfl_xor_sync(0xffffffffu, sB, 4);
        sA += __shfl_xor_sync(0xffffffffu, sA, 8);
        sB += __shfl_xor_sync(0xffffffffu, sB, 8);
        sA += __shfl_xor_sync(0xffffffffu, sA, 16);
        sB += __shfl_xor_sync(0xffffffffu, sB, 16);

        unsigned long long attA = pack2(sigmoid_fast(sA));
        unsigned long long attB = pack2(sigmoid_fast(sB));

        ulonglong2 c01 = *(const ulonglong2*)(cbp_s + j * H + 4 * qA);
        ulonglong2 c23 = *(const ulonglong2*)(cbp_s + j * H + 4 * qB);
        FMA2(csA[0], attA, c01.x);  FMA2(csA[1], attA, c01.y);
        FMA2(csA[2], attA, c23.x);  FMA2(csA[3], attA, c23.y);
        FMA2(csB[0], attB, c01.x);  FMA2(csB[1], attB, c01.y);
        FMA2(csB[2], attB, c23.x);  FMA2(csB[3], attB, c23.y);
    }

    // ---- phase 2: in-block projection ----
    __syncthreads();                 // everyone done reading up_s / cbp_s
    float* cs_s = cbp_s;             // 16 rows x 256, LOGICAL e' order
    // lane l holds csum element m (=0..7) -> logical e' = l + 32m
    {
        float* rowA = cs_s + wid * E;
        float* rowB = cs_s + (wid + 8) * E;
#pragma unroll
        for (int q = 0; q < 4; q++) {
            float2 fA = *(float2*)&csA[q];
            float2 fB = *(float2*)&csB[q];
            rowA[l + 32 * (2 * q)]     = fA.x;
            rowA[l + 32 * (2 * q + 1)] = fA.y;
            rowB[l + 32 * (2 * q)]     = fB.x;
            rowB[l + 32 * (2 * q + 1)] = fB.y;
        }
    }
    // stage Wp into the freed u region (straight copy, logical [e][h])
    float* wp_s = up_s;
#pragma unroll
    for (int it = 0; it < 16; it++)
        ((float4*)wp_s)[t + 256 * it] = __ldg(((const float4*)Wp) + t + 256 * it);
    __syncthreads();

    const int cg = t & 15, rg = t >> 4;   // 16 col-groups x 16 rows
    const int c0 = cg * 4;
    unsigned long long acc01 = 0, acc23 = 0;
#pragma unroll 4
    for (int e = 0; e < E; e++) {
        ulonglong2 w = *(const ulonglong2*)(wp_s + e * H + c0);
        unsigned long long cc = pack2(cs_s[rg * E + e]);
        FMA2(acc01, cc, w.x);  FMA2(acc23, cc, w.y);
    }

    // scatter flat rows: flat[scope[b*64+i]] = A[b,i]  (scope==0 -> pad, skip)
    float* flat = d_out + BS * H;
    {
        long long s = scope_at(scope, b * MA + qq * 16 + rg, is64);
        if (s > 0) {
            ulonglong2 o; o.x = acc01; o.y = acc23;
            *((ulonglong2*)(flat + s * H + c0)) = o;
        }
    }

    // ---- phase 3: molecule partial + deterministic last-block c_mol ----
    __syncthreads();                 // done reading cs_s -> reuse as 16x64 red
    {
        ulonglong2 o; o.x = acc01; o.y = acc23;
        *((ulonglong2*)(cs_s + rg * H + c0)) = o;
    }
    __syncthreads();
    if (t < H) {
        float s = 0.f;
#pragma unroll
        for (int g = 0; g < 16; g++) s += cs_s[g * H + t];
        g_molpart[(b * 4 + qq) * H + t] = s;
        __threadfence();             // make partial visible before counter bump
    }
    __syncthreads();
    if (t == 0) {
        int old = atomicAdd(&g_count[b], 1);
        flag = (old == 3);
    }
    __syncthreads();
    if (flag && t < H) {
        __threadfence();             // acquire side
        const float* mp = g_molpart + b * 4 * H + t;
        // fixed grouping -> bit-deterministic
        d_out[b * H + t] = (mp[0] + mp[H]) + (mp[2 * H] + mp[3 * H]);
    }
}

// ---------------------------------------------------------------------------
extern "C" void kernel_launch(void* const* d_in, const int* in_sizes, int n_in,
                              void* d_out, int out_size) {
    const float* inputs   = (const float*)d_in[0];
    const void*  scope    = d_in[1];
    // d_in[2] = scope_rev_tensor (unused: scatter via scope is its inverse)
    const float* Wa_pair  = (const float*)d_in[3];
    const float* Wa_score = (const float*)d_in[4];
    const float* Wp       = (const float*)d_in[5];
    float* out = (float*)d_out;

    const int n1 = in_sizes[0] / H;                            // N+1 flat rows
    const int smemA = (H * E + 8 * H) * (int)sizeof(float);    // 67584 B
    const int smemB = (MA * E + MA * H) * (int)sizeof(float);  // 81920 B
    cudaFuncSetAttribute(kA, cudaFuncAttributeMaxDynamicSharedMemorySize, smemA);
    cudaFuncSetAttribute(kB, cudaFuncAttributeMaxDynamicSharedMemorySize, smemB);

    kA<<<(n1 + 7) / 8, 256, smemA>>>(inputs, Wa_pair, n1, out);
    kB<<<dim3(BS, 4), 256, smemB>>>(inputs, scope, Wa_score, Wp, out);
}